// round 11
// baseline (speedup 1.0000x reference)
#include <cuda_runtime.h>

#define VOCAB   101
#define EMB     32
#define HID     32
#define T_STEPS 512
#define NWARP   16  // warps per block (512 threads); 8 warp-pairs
#define PAIRS   8
#define RPW     4   // rows per warp-pair

// Precomputed per-token gate contributions: tbl[v][j] = (i, f, g, o)
__device__ float4 g_tbl[VOCAB * HID];
// Packed recurrence weights (f32x2 across k):
// g_wpk[(gate*16 + k2)*32 + j] = ( Wh[2*k2][gate*32+j], Wh[2*k2+1][gate*32+j] )
// gate order: i, f, g, o
__device__ unsigned long long g_wpk[4 * 16 * 32];

__device__ __forceinline__ unsigned long long pack2(float lo, float hi) {
    unsigned long long r;
    asm("mov.b64 %0, {%1, %2};" : "=l"(r) : "f"(lo), "f"(hi));
    return r;
}
__device__ __forceinline__ float lo2(unsigned long long v) {
    return __uint_as_float((unsigned int)v);
}
__device__ __forceinline__ float hi2(unsigned long long v) {
    return __uint_as_float((unsigned int)(v >> 32));
}
// Packed double-rate fp32 FMA (Blackwell FFMA2)
__device__ __forceinline__ unsigned long long ffma2(unsigned long long a,
                                                    unsigned long long b,
                                                    unsigned long long c) {
    unsigned long long d;
    asm("fma.rn.f32x2 %0, %1, %2, %3;" : "=l"(d) : "l"(a), "l"(b), "l"(c));
    return d;
}
__device__ __forceinline__ float tanh_fast(float x) {
    float y;
    asm("tanh.approx.f32 %0, %1;" : "=f"(y) : "f"(x));
    return y;
}
__device__ __forceinline__ float sigmoid_fast(float x) {
    return fmaf(0.5f, tanh_fast(0.5f * x), 0.5f);
}
__device__ __forceinline__ void bar_pair(int id) {
    asm volatile("bar.sync %0, 64;" :: "r"(id) : "memory");
}

// ---------------------------------------------------------------------------
// Prep: token->xgate table and packed Wh. Tiny.
// ---------------------------------------------------------------------------
__global__ void prep_kernel(const float* __restrict__ emb,
                            const float* __restrict__ Wx,
                            const float* __restrict__ b,
                            const float* __restrict__ Wh) {
    int tid = blockIdx.x * blockDim.x + threadIdx.x;
    if (tid < VOCAB * HID) {
        int v = tid / HID, j = tid % HID;
        float si = b[j], sf = b[HID + j], sg = b[2 * HID + j], so = b[3 * HID + j];
        #pragma unroll
        for (int e = 0; e < EMB; e++) {
            float xe = emb[v * EMB + e];
            si = fmaf(xe, Wx[e * 4 * HID + j], si);
            sf = fmaf(xe, Wx[e * 4 * HID + HID + j], sf);
            sg = fmaf(xe, Wx[e * 4 * HID + 2 * HID + j], sg);
            so = fmaf(xe, Wx[e * 4 * HID + 3 * HID + j], so);
        }
        g_tbl[tid] = make_float4(si, sf, sg, so);
    }
    if (tid < 4 * 16 * 32) {
        int j  = tid & 31;
        int k2 = (tid >> 5) & 15;
        int g  = tid >> 9;
        float w0 = Wh[(2 * k2) * 4 * HID + g * HID + j];
        float w1 = Wh[(2 * k2 + 1) * 4 * HID + g * HID + j];
        g_wpk[tid] = pack2(w0, w1);
    }
}

// ---------------------------------------------------------------------------
// Main: warp-specialized gate-split. A warp PAIR shares 4 batch rows.
//   role 0 (warp A): gates i,f  -> writes pre-activations to smem
//   role 1 (warp B): gates g,o  -> owns c/h state, does activations, writes h
// Each warp holds only HALF the Wh columns (64 regs), enabling 16 warps/SM.
// Both roles execute the identical FFMA2 accumulation loop (shared I$ body).
// Two named 64-thread barriers per timestep. Ping-pong h buffers.
// ---------------------------------------------------------------------------
__global__ void __launch_bounds__(NWARP * 32, 1)
lstm_kernel(const int* __restrict__ x,
            const float* __restrict__ Wfc,
            const float* __restrict__ bfc,
            float* __restrict__ out, int B) {
    const unsigned FULL = 0xffffffffu;
    const int lane = threadIdx.x & 31;
    const int wid  = threadIdx.x >> 5;
    const int pid  = wid >> 1;          // pair id 0..7
    const int role = wid & 1;           // 0 = i,f producer; 1 = g,o + state
    const int barid = pid + 1;          // named barriers 1..8

    const int rs = (blockIdx.x * PAIRS + pid) * RPW;   // first row of this pair

    __shared__ __align__(16) float  hsm[PAIRS][2][RPW][HID];  // ping-pong h
    __shared__ __align__(8)  float2 gsm[PAIRS][RPW][HID];     // (gi, gf)

    // half the packed weights: role 0 -> gates i,f ; role 1 -> gates g,o
    unsigned long long w[32];
    #pragma unroll
    for (int i = 0; i < 32; i++) w[i] = g_wpk[(role * 32 + i) * 32 + lane];

    // row offsets (clamped for dummy slots)
    int off[RPW];
    #pragma unroll
    for (int r = 0; r < RPW; ++r) {
        int bb = rs + r; if (bb >= B) bb = B - 1;
        off[r] = bb * T_STEPS;
    }

    float c[RPW], hl[RPW];
    #pragma unroll
    for (int r = 0; r < RPW; ++r) { c[r] = 0.f; hl[r] = 0.f; }

    if (role == 1) {
        #pragma unroll
        for (int r = 0; r < RPW; ++r) hsm[pid][0][r][lane] = 0.f;
    }
    bar_pair(barid);

    for (int tc = 0; tc < T_STEPS / 32; ++tc) {
        int tokr[RPW];
        #pragma unroll
        for (int r = 0; r < RPW; ++r) tokr[r] = x[off[r] + tc * 32 + lane];

        #pragma unroll 2
        for (int s = 0; s < 32; ++s) {
            const int buf = s & 1;

            // this role's half of the token table: (i,f) or (g,o)
            float2 tb[RPW];
            #pragma unroll
            for (int r = 0; r < RPW; ++r) {
                int tok = __shfl_sync(FULL, tokr[r], s);
                tb[r] = __ldg((const float2*)&g_tbl[tok * HID + lane] + role);
            }

            // shared accumulation loop (identical code for both roles)
            unsigned long long acc[RPW][2];
            #pragma unroll
            for (int r = 0; r < RPW; ++r) acc[r][0] = acc[r][1] = 0ull;

            // row r = ulonglong2 indices [r*8, r*8+7]  (32 floats / 4 per 16B)
            const ulonglong2* hb = (const ulonglong2*)hsm[pid][buf];
            #pragma unroll
            for (int k4 = 0; k4 < 8; ++k4) {
                #pragma unroll
                for (int r = 0; r < RPW; ++r) {
                    ulonglong2 hq = hb[r * 8 + k4];      // broadcast LDS.128
                    acc[r][0] = ffma2(hq.x, w[     2 * k4    ], acc[r][0]);
                    acc[r][0] = ffma2(hq.y, w[     2 * k4 + 1], acc[r][0]);
                    acc[r][1] = ffma2(hq.x, w[16 + 2 * k4    ], acc[r][1]);
                    acc[r][1] = ffma2(hq.y, w[16 + 2 * k4 + 1], acc[r][1]);
                }
            }

            if (role == 0) {
                // producer: write pre-activation (gi, gf)
                #pragma unroll
                for (int r = 0; r < RPW; ++r) {
                    float gi = tb[r].x + (lo2(acc[r][0]) + hi2(acc[r][0]));
                    float gf = tb[r].y + (lo2(acc[r][1]) + hi2(acc[r][1]));
                    gsm[pid][r][lane] = make_float2(gi, gf);
                }
                bar_pair(barid);   // g ready
                bar_pair(barid);   // h ready (written by role 1)
            } else {
                float gg[RPW], go[RPW];
                #pragma unroll
                for (int r = 0; r < RPW; ++r) {
                    gg[r] = tb[r].x + (lo2(acc[r][0]) + hi2(acc[r][0]));
                    go[r] = tb[r].y + (lo2(acc[r][1]) + hi2(acc[r][1]));
                }
                bar_pair(barid);   // wait for (gi, gf)
                #pragma unroll
                for (int r = 0; r < RPW; ++r) {
                    float2 gif = gsm[pid][r][lane];
                    float is = sigmoid_fast(gif.x);
                    float fs = sigmoid_fast(gif.y);
                    float gt = tanh_fast(gg[r]);
                    float os = sigmoid_fast(go[r]);
                    c[r] = fmaf(fs, c[r], is * gt);
                    float h = os * tanh_fast(c[r]);
                    hl[r] = h;
                    hsm[pid][buf ^ 1][r][lane] = h;
                }
                bar_pair(barid);   // h published
            }
        }
    }

    // FC head (role 1 owns h): out[b] = h @ W_fc + b_fc
    if (role == 1) {
        float wf0 = Wfc[lane * 2 + 0], wf1 = Wfc[lane * 2 + 1];
        #pragma unroll
        for (int r = 0; r < RPW; ++r) {
            float u0 = hl[r] * wf0;
            float u1 = hl[r] * wf1;
            #pragma unroll
            for (int o = 16; o; o >>= 1) {
                u0 += __shfl_xor_sync(FULL, u0, o);
                u1 += __shfl_xor_sync(FULL, u1, o);
            }
            if (lane == 0 && rs + r < B) {
                out[(rs + r) * 2 + 0] = u0 + bfc[0];
                out[(rs + r) * 2 + 1] = u1 + bfc[1];
            }
        }
    }
}

// ---------------------------------------------------------------------------
// Harness entry
// Inputs: x[int32 B*T], emb[101*32], Wx[32*128], Wh[32*128], b[128],
//         W_fc[32*2], b_fc[2]. Output: float [B,2].
// ---------------------------------------------------------------------------
extern "C" void kernel_launch(void* const* d_in, const int* in_sizes, int n_in,
                              void* d_out, int out_size) {
    const int*   x   = (const int*)  d_in[0];
    const float* emb = (const float*)d_in[1];
    const float* Wx  = (const float*)d_in[2];
    const float* Wh  = (const float*)d_in[3];
    const float* b   = (const float*)d_in[4];
    const float* Wfc = (const float*)d_in[5];
    const float* bfc = (const float*)d_in[6];
    float* out = (float*)d_out;

    const int B = in_sizes[0] / T_STEPS;

    prep_kernel<<<(VOCAB * HID + 255) / 256, 256>>>(emb, Wx, b, Wh);

    // uniform grid: every block = 8 pairs x 4 rows = 32 row-slots
    int nblocks = (B + PAIRS * RPW - 1) / (PAIRS * RPW);  // 128 for B=4096
    lstm_kernel<<<nblocks, NWARP * 32>>>(x, Wfc, bfc, out, B);
}

// round 12
// speedup vs baseline: 1.2737x; 1.2737x over previous
#include <cuda_runtime.h>

#define VOCAB   101
#define EMB     32
#define HID     32
#define T_STEPS 512
#define NWARP   4   // warps per block = 1 per SMSP
#define RPW     7   // batch rows per warp

// Precomputed per-token gate contributions: tbl[v][j] = (i, f, g, o)
__device__ float4 g_tbl[VOCAB * HID];
// Packed recurrence weights (f32x2 across k):
// g_wpk[(gate*16 + k2)*32 + j] = ( Wh[2*k2][gate*32+j], Wh[2*k2+1][gate*32+j] )
__device__ unsigned long long g_wpk[4 * 16 * 32];

__device__ __forceinline__ unsigned long long pack2(float lo, float hi) {
    unsigned long long r;
    asm("mov.b64 %0, {%1, %2};" : "=l"(r) : "f"(lo), "f"(hi));
    return r;
}
__device__ __forceinline__ float lo2(unsigned long long v) {
    return __uint_as_float((unsigned int)v);
}
__device__ __forceinline__ float hi2(unsigned long long v) {
    return __uint_as_float((unsigned int)(v >> 32));
}
// Packed double-rate fp32 FMA (Blackwell FFMA2)
__device__ __forceinline__ unsigned long long ffma2(unsigned long long a,
                                                    unsigned long long b,
                                                    unsigned long long c) {
    unsigned long long d;
    asm("fma.rn.f32x2 %0, %1, %2, %3;" : "=l"(d) : "l"(a), "l"(b), "l"(c));
    return d;
}
__device__ __forceinline__ float tanh_fast(float x) {
    float y;
    asm("tanh.approx.f32 %0, %1;" : "=f"(y) : "f"(x));
    return y;
}
__device__ __forceinline__ float sigmoid_fast(float x) {
    return fmaf(0.5f, tanh_fast(0.5f * x), 0.5f);
}

// ---------------------------------------------------------------------------
// Prep: token->xgate table and packed Wh. Tiny.
// ---------------------------------------------------------------------------
__global__ void prep_kernel(const float* __restrict__ emb,
                            const float* __restrict__ Wx,
                            const float* __restrict__ b,
                            const float* __restrict__ Wh) {
    int tid = blockIdx.x * blockDim.x + threadIdx.x;
    if (tid < VOCAB * HID) {
        int v = tid / HID, j = tid % HID;
        float si = b[j], sf = b[HID + j], sg = b[2 * HID + j], so = b[3 * HID + j];
        #pragma unroll
        for (int e = 0; e < EMB; e++) {
            float xe = emb[v * EMB + e];
            si = fmaf(xe, Wx[e * 4 * HID + j], si);
            sf = fmaf(xe, Wx[e * 4 * HID + HID + j], sf);
            sg = fmaf(xe, Wx[e * 4 * HID + 2 * HID + j], sg);
            so = fmaf(xe, Wx[e * 4 * HID + 3 * HID + j], so);
        }
        g_tbl[tid] = make_float4(si, sf, sg, so);
    }
    if (tid < 4 * 16 * 32) {
        int j  = tid & 31;
        int k2 = (tid >> 5) & 15;
        int g  = tid >> 9;
        float w0 = Wh[(2 * k2) * 4 * HID + g * HID + j];
        float w1 = Wh[(2 * k2 + 1) * 4 * HID + g * HID + j];
        g_wpk[tid] = pack2(w0, w1);
    }
}

// ---------------------------------------------------------------------------
// Main: ONE warp per SMSP (4 warps / 128 threads per block), each warp owns
// SEVEN batch rows. Lane j owns hidden unit j of every row. The warp has the
// whole SMSP issue bandwidth; 7 independent row-chains provide the ILP that
// other warps used to (fail to) provide. h via ping-pong smem broadcast
// (LDS.128), Wh columns in registers, matvec in packed f32x2 (FFMA2).
// 147 blocks x 4 warps x 7 rows = 4116 row slots >= 4096 (single wave).
// ---------------------------------------------------------------------------
__global__ void __launch_bounds__(NWARP * 32, 1)
lstm_kernel(const int* __restrict__ x,
            const float* __restrict__ Wfc,
            const float* __restrict__ bfc,
            float* __restrict__ out, int B) {
    const unsigned FULL = 0xffffffffu;
    const int lane = threadIdx.x & 31;
    const int wid  = threadIdx.x >> 5;
    const int rs = (blockIdx.x * NWARP + wid) * RPW;   // first row of this warp

    // ping-pong h buffers: [warp][parity][row][unit]
    __shared__ __align__(16) float hsm[NWARP][2][RPW][HID];

    // 64 packed weight words (128 fp32), shared by all 7 rows
    unsigned long long w[64];
    #pragma unroll
    for (int i = 0; i < 64; i++) w[i] = g_wpk[i * 32 + lane];

    #pragma unroll
    for (int r = 0; r < RPW; ++r) hsm[wid][0][r][lane] = 0.f;
    __syncwarp();

    float c[RPW];
    #pragma unroll
    for (int r = 0; r < RPW; ++r) c[r] = 0.f;

    // clamped row base offsets (dummy slots replay row B-1; writes guarded)
    const int* xrow[RPW];
    #pragma unroll
    for (int r = 0; r < RPW; ++r) {
        int bb = rs + r; if (bb >= B) bb = B - 1;
        xrow[r] = x + (long long)bb * T_STEPS;
    }

    for (int tc = 0; tc < T_STEPS / 32; ++tc) {
        int tokr[RPW];
        #pragma unroll
        for (int r = 0; r < RPW; ++r) tokr[r] = xrow[r][tc * 32 + lane];

        for (int s = 0; s < 32; ++s) {
            const int buf = s & 1;

            // table loads first: LDG latency hides under the FMA loop
            float4 tb[RPW];
            #pragma unroll
            for (int r = 0; r < RPW; ++r) {
                int tok = __shfl_sync(FULL, tokr[r], s);
                tb[r] = __ldg(&g_tbl[tok * HID + lane]);
            }

            unsigned long long acc[RPW][4];
            #pragma unroll
            for (int r = 0; r < RPW; ++r)
                acc[r][0] = acc[r][1] = acc[r][2] = acc[r][3] = 0ull;

            // row r occupies ulonglong2 indices [r*8, r*8+7]
            const ulonglong2* hb = (const ulonglong2*)hsm[wid][buf];
            #pragma unroll
            for (int k4 = 0; k4 < 8; ++k4) {
                #pragma unroll
                for (int r = 0; r < RPW; ++r) {
                    ulonglong2 hq = hb[r * 8 + k4];      // broadcast LDS.128
                    acc[r][0] = ffma2(hq.x, w[     2 * k4    ], acc[r][0]);
                    acc[r][0] = ffma2(hq.y, w[     2 * k4 + 1], acc[r][0]);
                    acc[r][1] = ffma2(hq.x, w[16 + 2 * k4    ], acc[r][1]);
                    acc[r][1] = ffma2(hq.y, w[16 + 2 * k4 + 1], acc[r][1]);
                    acc[r][2] = ffma2(hq.x, w[32 + 2 * k4    ], acc[r][2]);
                    acc[r][2] = ffma2(hq.y, w[32 + 2 * k4 + 1], acc[r][2]);
                    acc[r][3] = ffma2(hq.x, w[48 + 2 * k4    ], acc[r][3]);
                    acc[r][3] = ffma2(hq.y, w[48 + 2 * k4 + 1], acc[r][3]);
                }
            }

            #pragma unroll
            for (int r = 0; r < RPW; ++r) {
                float gi = tb[r].x + (lo2(acc[r][0]) + hi2(acc[r][0]));
                float gf = tb[r].y + (lo2(acc[r][1]) + hi2(acc[r][1]));
                float gg = tb[r].z + (lo2(acc[r][2]) + hi2(acc[r][2]));
                float go = tb[r].w + (lo2(acc[r][3]) + hi2(acc[r][3]));
                float is = sigmoid_fast(gi);
                float fs = sigmoid_fast(gf);
                float os = sigmoid_fast(go);
                float gt = tanh_fast(gg);
                c[r] = fmaf(fs, c[r], is * gt);
                float h = os * tanh_fast(c[r]);
                hsm[wid][buf ^ 1][r][lane] = h;          // publish next-step h
            }
            __syncwarp();
        }
    }

    // FC head: final h is in buffer 0 (last step s=31 wrote buf^1 = 0)
    float wf0 = Wfc[lane * 2 + 0], wf1 = Wfc[lane * 2 + 1];
    #pragma unroll
    for (int r = 0; r < RPW; ++r) {
        float h = hsm[wid][0][r][lane];
        float u0 = h * wf0;
        float u1 = h * wf1;
        #pragma unroll
        for (int o = 16; o; o >>= 1) {
            u0 += __shfl_xor_sync(FULL, u0, o);
            u1 += __shfl_xor_sync(FULL, u1, o);
        }
        if (lane == 0 && rs + r < B) {
            out[(rs + r) * 2 + 0] = u0 + bfc[0];
            out[(rs + r) * 2 + 1] = u1 + bfc[1];
        }
    }
}

// ---------------------------------------------------------------------------
// Harness entry
// Inputs: x[int32 B*T], emb[101*32], Wx[32*128], Wh[32*128], b[128],
//         W_fc[32*2], b_fc[2]. Output: float [B,2].
// ---------------------------------------------------------------------------
extern "C" void kernel_launch(void* const* d_in, const int* in_sizes, int n_in,
                              void* d_out, int out_size) {
    const int*   x   = (const int*)  d_in[0];
    const float* emb = (const float*)d_in[1];
    const float* Wx  = (const float*)d_in[2];
    const float* Wh  = (const float*)d_in[3];
    const float* b   = (const float*)d_in[4];
    const float* Wfc = (const float*)d_in[5];
    const float* bfc = (const float*)d_in[6];
    float* out = (float*)d_out;

    const int B = in_sizes[0] / T_STEPS;

    prep_kernel<<<(VOCAB * HID + 255) / 256, 256>>>(emb, Wx, b, Wh);

    // ceil(B / (4 warps * 7 rows)) = 147 blocks for B=4096 -> single wave
    const int nblocks = (B + NWARP * RPW - 1) / (NWARP * RPW);
    lstm_kernel<<<nblocks, NWARP * 32>>>(x, Wfc, bfc, out, B);
}

// round 13
// speedup vs baseline: 1.4397x; 1.1303x over previous
#include <cuda_runtime.h>

#define VOCAB   101
#define EMB     32
#define HID     32
#define T_STEPS 512
#define NWARP   8   // 8 warps/block: SMSP s gets warp s (4 rows) + warp s+4 (3 rows)
#define RPB     28  // rows per block = 4*(4+3)

// Precomputed per-token gate contributions: tbl[v][j] = (i, f, g, o)
__device__ float4 g_tbl[VOCAB * HID];
// Packed recurrence weights (f32x2 across k):
// g_wpk[(gate*16 + k2)*32 + j] = ( Wh[2*k2][gate*32+j], Wh[2*k2+1][gate*32+j] )
__device__ unsigned long long g_wpk[4 * 16 * 32];

__device__ __forceinline__ unsigned long long pack2(float lo, float hi) {
    unsigned long long r;
    asm("mov.b64 %0, {%1, %2};" : "=l"(r) : "f"(lo), "f"(hi));
    return r;
}
__device__ __forceinline__ float lo2(unsigned long long v) {
    return __uint_as_float((unsigned int)v);
}
__device__ __forceinline__ float hi2(unsigned long long v) {
    return __uint_as_float((unsigned int)(v >> 32));
}
// Packed double-rate fp32 FMA (Blackwell FFMA2)
__device__ __forceinline__ unsigned long long ffma2(unsigned long long a,
                                                    unsigned long long b,
                                                    unsigned long long c) {
    unsigned long long d;
    asm("fma.rn.f32x2 %0, %1, %2, %3;" : "=l"(d) : "l"(a), "l"(b), "l"(c));
    return d;
}
__device__ __forceinline__ float tanh_fast(float x) {
    float y;
    asm("tanh.approx.f32 %0, %1;" : "=f"(y) : "f"(x));
    return y;
}
__device__ __forceinline__ float sigmoid_fast(float x) {
    return fmaf(0.5f, tanh_fast(0.5f * x), 0.5f);
}

// ---------------------------------------------------------------------------
// Prep: token->xgate table and packed Wh. Tiny.
// ---------------------------------------------------------------------------
__global__ void prep_kernel(const float* __restrict__ emb,
                            const float* __restrict__ Wx,
                            const float* __restrict__ b,
                            const float* __restrict__ Wh) {
    int tid = blockIdx.x * blockDim.x + threadIdx.x;
    if (tid < VOCAB * HID) {
        int v = tid / HID, j = tid % HID;
        float si = b[j], sf = b[HID + j], sg = b[2 * HID + j], so = b[3 * HID + j];
        #pragma unroll
        for (int e = 0; e < EMB; e++) {
            float xe = emb[v * EMB + e];
            si = fmaf(xe, Wx[e * 4 * HID + j], si);
            sf = fmaf(xe, Wx[e * 4 * HID + HID + j], sf);
            sg = fmaf(xe, Wx[e * 4 * HID + 2 * HID + j], sg);
            so = fmaf(xe, Wx[e * 4 * HID + 3 * HID + j], so);
        }
        g_tbl[tid] = make_float4(si, sf, sg, so);
    }
    if (tid < 4 * 16 * 32) {
        int j  = tid & 31;
        int k2 = (tid >> 5) & 15;
        int g  = tid >> 9;
        float w0 = Wh[(2 * k2) * 4 * HID + g * HID + j];
        float w1 = Wh[(2 * k2 + 1) * 4 * HID + g * HID + j];
        g_wpk[tid] = pack2(w0, w1);
    }
}

// ---------------------------------------------------------------------------
// Per-warp LSTM over RPW rows. Lane j owns hidden unit j of each row.
// Token gate table read from SHARED memory; accumulators initialized with it
// (shorter tail). h ping-pong in smem, read as broadcast LDS.128 (pre-packed
// f32x2 pairs). Wh columns in registers, matvec in packed FFMA2.
// ---------------------------------------------------------------------------
template <int RPW>
__device__ __forceinline__ void lstm_rows(
    const int* __restrict__ x,
    const float* __restrict__ Wfc,
    const float* __restrict__ bfc,
    float* __restrict__ out,
    int rs, int lane, int B,
    const float4* __restrict__ tbl_s,
    float (&hsm)[2][4][HID],
    const unsigned long long (&w)[64])
{
    const unsigned FULL = 0xffffffffu;

    #pragma unroll
    for (int r = 0; r < RPW; ++r) hsm[0][r][lane] = 0.f;
    __syncwarp();

    float c[RPW];
    #pragma unroll
    for (int r = 0; r < RPW; ++r) c[r] = 0.f;

    const int* xrow[RPW];
    #pragma unroll
    for (int r = 0; r < RPW; ++r) {
        int bb = rs + r; if (bb >= B) bb = B - 1;   // dummy slots clamp
        xrow[r] = x + (long long)bb * T_STEPS;
    }

    for (int tc = 0; tc < T_STEPS / 32; ++tc) {
        int tokr[RPW];
        #pragma unroll
        for (int r = 0; r < RPW; ++r) tokr[r] = xrow[r][tc * 32 + lane];

        #pragma unroll 2
        for (int s = 0; s < 32; ++s) {
            const int buf = s & 1;

            // gate bases from smem table; init accumulators with them
            unsigned long long acc[RPW][4];
            #pragma unroll
            for (int r = 0; r < RPW; ++r) {
                int tok = __shfl_sync(FULL, tokr[r], s);
                float4 tb = tbl_s[tok * HID + lane];     // broadcast-row LDS.128
                acc[r][0] = pack2(tb.x, 0.f);
                acc[r][1] = pack2(tb.y, 0.f);
                acc[r][2] = pack2(tb.z, 0.f);
                acc[r][3] = pack2(tb.w, 0.f);
            }

            // row r occupies ulonglong2 indices [r*8, r*8+7]
            const ulonglong2* hb = (const ulonglong2*)hsm[buf];
            #pragma unroll
            for (int k4 = 0; k4 < 8; ++k4) {
                #pragma unroll
                for (int r = 0; r < RPW; ++r) {
                    ulonglong2 hq = hb[r * 8 + k4];      // broadcast LDS.128
                    acc[r][0] = ffma2(hq.x, w[     2 * k4    ], acc[r][0]);
                    acc[r][0] = ffma2(hq.y, w[     2 * k4 + 1], acc[r][0]);
                    acc[r][1] = ffma2(hq.x, w[16 + 2 * k4    ], acc[r][1]);
                    acc[r][1] = ffma2(hq.y, w[16 + 2 * k4 + 1], acc[r][1]);
                    acc[r][2] = ffma2(hq.x, w[32 + 2 * k4    ], acc[r][2]);
                    acc[r][2] = ffma2(hq.y, w[32 + 2 * k4 + 1], acc[r][2]);
                    acc[r][3] = ffma2(hq.x, w[48 + 2 * k4    ], acc[r][3]);
                    acc[r][3] = ffma2(hq.y, w[48 + 2 * k4 + 1], acc[r][3]);
                }
            }

            #pragma unroll
            for (int r = 0; r < RPW; ++r) {
                float gi = lo2(acc[r][0]) + hi2(acc[r][0]);
                float gf = lo2(acc[r][1]) + hi2(acc[r][1]);
                float gg = lo2(acc[r][2]) + hi2(acc[r][2]);
                float go = lo2(acc[r][3]) + hi2(acc[r][3]);
                float is = sigmoid_fast(gi);
                float fs = sigmoid_fast(gf);
                float os = sigmoid_fast(go);
                float gt = tanh_fast(gg);
                c[r] = fmaf(fs, c[r], is * gt);
                float h = os * tanh_fast(c[r]);
                hsm[buf ^ 1][r][lane] = h;              // publish next-step h
            }
            __syncwarp();
        }
    }

    // FC head: final h sits in buffer 0
    float wf0 = Wfc[lane * 2 + 0], wf1 = Wfc[lane * 2 + 1];
    #pragma unroll
    for (int r = 0; r < RPW; ++r) {
        float h = hsm[0][r][lane];
        float u0 = h * wf0;
        float u1 = h * wf1;
        #pragma unroll
        for (int o = 16; o; o >>= 1) {
            u0 += __shfl_xor_sync(FULL, u0, o);
            u1 += __shfl_xor_sync(FULL, u1, o);
        }
        if (lane == 0 && rs + r < B) {
            out[(rs + r) * 2 + 0] = u0 + bfc[0];
            out[(rs + r) * 2 + 1] = u1 + bfc[1];
        }
    }
}

// ---------------------------------------------------------------------------
// Main: asymmetric warp pairing — SMSP s hosts warp s (4 rows) and warp s+4
// (3 rows) -> exactly 7 rows per SMSP, 28 per SM, 147 blocks = single wave
// covering B=4096 with uniform per-SM load. Two template bodies only.
// ---------------------------------------------------------------------------
__global__ void __launch_bounds__(NWARP * 32, 1)
lstm_kernel(const int* __restrict__ x,
            const float* __restrict__ Wfc,
            const float* __restrict__ bfc,
            float* __restrict__ out, int B) {
    const int lane = threadIdx.x & 31;
    const int wid  = threadIdx.x >> 5;

    // token table in shared memory (101*32 float4 = 51.7 KB)
    __shared__ __align__(16) float4 tbl_s[VOCAB * HID];
    // ping-pong h buffers per warp
    __shared__ __align__(16) float hsm[NWARP][2][4][HID];

    for (int i = threadIdx.x; i < VOCAB * HID; i += NWARP * 32)
        tbl_s[i] = g_tbl[i];

    // 64 packed weight words (128 fp32), shared by all rows of this warp
    unsigned long long w[64];
    #pragma unroll
    for (int i = 0; i < 64; i++) w[i] = g_wpk[i * 32 + lane];

    __syncthreads();   // table ready

    const int base = blockIdx.x * RPB;
    if (wid < 4) {
        int rs = base + wid * 4;                 // 4-row warps: rows [base, base+16)
        lstm_rows<4>(x, Wfc, bfc, out, rs, lane, B, tbl_s, hsm[wid], w);
    } else {
        int rs = base + 16 + (wid - 4) * 3;      // 3-row warps: rows [base+16, base+28)
        lstm_rows<3>(x, Wfc, bfc, out, rs, lane, B, tbl_s, hsm[wid], w);
    }
}

// ---------------------------------------------------------------------------
// Harness entry
// Inputs: x[int32 B*T], emb[101*32], Wx[32*128], Wh[32*128], b[128],
//         W_fc[32*2], b_fc[2]. Output: float [B,2].
// ---------------------------------------------------------------------------
extern "C" void kernel_launch(void* const* d_in, const int* in_sizes, int n_in,
                              void* d_out, int out_size) {
    const int*   x   = (const int*)  d_in[0];
    const float* emb = (const float*)d_in[1];
    const float* Wx  = (const float*)d_in[2];
    const float* Wh  = (const float*)d_in[3];
    const float* b   = (const float*)d_in[4];
    const float* Wfc = (const float*)d_in[5];
    const float* bfc = (const float*)d_in[6];
    float* out = (float*)d_out;

    const int B = in_sizes[0] / T_STEPS;

    prep_kernel<<<(VOCAB * HID + 255) / 256, 256>>>(emb, Wx, b, Wh);

    const int nblocks = (B + RPB - 1) / RPB;   // 147 for B=4096 -> single wave
    lstm_kernel<<<nblocks, NWARP * 32>>>(x, Wfc, bfc, out, B);
}